// round 3
// baseline (speedup 1.0000x reference)
#include <cuda_runtime.h>
#include <math.h>

#define BB 2
#define PP 2048
#define MM 1024
#define NHEAD 16
#define HD 64

// Scratch (static device globals: allocation-guard safe)
__device__ float g_q[BB*NHEAD*PP*HD];   // [B,N,P,H]
__device__ float g_k[BB*NHEAD*PP*HD];
__device__ float g_v[BB*NHEAD*PP*HD];
__device__ float g_z[BB*PP*NHEAD*HD];   // [B,P,N,H]  (contiguous [4096 x 1024])

// ---------------------------------------------------------------------------
// QKV projection GEMM: dst[b,n,p,h] = sum_m x[b,p,m] * w[n,m,h] + bias[n,h]
// DST template selects g_q / g_k / g_v (no cudaGetSymbolAddress in launch).
// Tile: 128 rows (b*p) x 64 cols (one head). 256 threads, 8x4 per thread.
// ---------------------------------------------------------------------------
template<int DST>
__global__ __launch_bounds__(256) void qkv_kernel(
    const float* __restrict__ x, const float* __restrict__ w,
    const float* __restrict__ bias)
{
    __shared__ float As[16*132];   // transposed: As[k][m], padded
    __shared__ float Bs[16*68];    // Bs[k][h], padded

    const int n  = blockIdx.x;          // head == column tile
    const int r0 = blockIdx.y * 128;    // row tile over B*P
    const int tid = threadIdx.x;
    const int tx = tid & 15, ty = tid >> 4;
    const float* wh = w + n * MM * HD;

    float acc[8][4] = {};

    for (int k0 = 0; k0 < MM; k0 += 16) {
        // A tile 128x16 -> transposed smem
        #pragma unroll
        for (int t = 0; t < 2; t++) {
            int idx = tid + t*256;
            int r = idx >> 2, kc = (idx & 3) * 4;
            float4 v4 = *(const float4*)&x[(r0 + r)*MM + k0 + kc];
            As[(kc+0)*132 + r] = v4.x;
            As[(kc+1)*132 + r] = v4.y;
            As[(kc+2)*132 + r] = v4.z;
            As[(kc+3)*132 + r] = v4.w;
        }
        {   // B tile 16x64
            int kr = tid >> 4, c4 = (tid & 15) * 4;
            *(float4*)&Bs[kr*68 + c4] = *(const float4*)&wh[(k0+kr)*HD + c4];
        }
        __syncthreads();
        #pragma unroll
        for (int kk = 0; kk < 16; kk++) {
            float4 a0 = *(float4*)&As[kk*132 + ty*8];
            float4 a1 = *(float4*)&As[kk*132 + ty*8 + 4];
            float4 b0 = *(float4*)&Bs[kk*68 + tx*4];
            float ar[8] = {a0.x,a0.y,a0.z,a0.w,a1.x,a1.y,a1.z,a1.w};
            float br[4] = {b0.x,b0.y,b0.z,b0.w};
            #pragma unroll
            for (int i = 0; i < 8; i++)
                #pragma unroll
                for (int j = 0; j < 4; j++)
                    acc[i][j] = fmaf(ar[i], br[j], acc[i][j]);
        }
        __syncthreads();
    }
    float* outp = (DST == 0) ? g_q : (DST == 1) ? g_k : g_v;
    #pragma unroll
    for (int i = 0; i < 8; i++) {
        int r = r0 + ty*8 + i;
        int b = r >> 11, p = r & 2047;     // P = 2048
        float* dst = &outp[(((b*NHEAD + n)*PP + p)*HD) + tx*4];
        #pragma unroll
        for (int j = 0; j < 4; j++)
            dst[j] = acc[i][j] + bias[n*HD + tx*4 + j];
    }
}

// ---------------------------------------------------------------------------
// Fused attention: per (b,n, 128-row q tile), loop 64-key tiles from k0 = q0.
// Mask keeps STRICTLY-UPPER triangle (k > q); masked entries are exactly -1e10.
// Online softmax in registers; row reductions via 16-lane shfl.
// ---------------------------------------------------------------------------
#define SMQ 0                       // Qs_t [64][132]  (feature-major)
#define SMK (64*132)                // Ks_t [64][68]   (feature-major)
#define SMV (SMK + 64*68)           // Vs   [64][68]   (key-major)
#define SMP (SMV + 64*68)           // Ps_t [64][132]  (key-major, rows=q)
#define SM_FLOATS (SMP + 64*132)

extern __shared__ float sm_attn[];

__global__ __launch_bounds__(256, 2) void attn_kernel()
{
    const int q0 = blockIdx.x * 128;
    const int bn = blockIdx.y;          // b*NHEAD + n
    const int base = bn * PP * HD;
    const int tid = threadIdx.x;
    const int tx = tid & 15, ty = tid >> 4;

    float* Qs = sm_attn + SMQ;
    float* Ks = sm_attn + SMK;
    float* Vs = sm_attn + SMV;
    float* Ps = sm_attn + SMP;

    // Load Q tile [128][64] transposed -> Qs_t[f][r]
    #pragma unroll
    for (int t = 0; t < 8; t++) {
        int idx = tid + t*256;
        int r = idx >> 4, f = (idx & 15) * 4;
        float4 v4 = *(const float4*)&g_q[base + (q0 + r)*HD + f];
        Qs[(f+0)*132 + r] = v4.x;
        Qs[(f+1)*132 + r] = v4.y;
        Qs[(f+2)*132 + r] = v4.z;
        Qs[(f+3)*132 + r] = v4.w;
    }

    float m_i[8], l_i[8], O[8][4];
    #pragma unroll
    for (int i = 0; i < 8; i++) {
        m_i[i] = -1e30f; l_i[i] = 0.f;
        #pragma unroll
        for (int j = 0; j < 4; j++) O[i][j] = 0.f;
    }

    // Only tiles with some k > q0 matter (tiles with k_max <= q0 contribute
    // exactly 0 for every row except the fully-masked row q=P-1, fixed later).
    for (int k0 = q0; k0 < PP; k0 += 64) {
        __syncthreads();   // prior PV done (covers Q-load visibility on iter 0)
        // Load K tile transposed, V tile direct
        #pragma unroll
        for (int t = 0; t < 4; t++) {
            int idx = tid + t*256;
            int c = idx >> 4, f = (idx & 15) * 4;
            float4 kv = *(const float4*)&g_k[base + (k0 + c)*HD + f];
            Ks[(f+0)*68 + c] = kv.x;
            Ks[(f+1)*68 + c] = kv.y;
            Ks[(f+2)*68 + c] = kv.z;
            Ks[(f+3)*68 + c] = kv.w;
            float4 vv = *(const float4*)&g_v[base + (k0 + c)*HD + f];
            *(float4*)&Vs[c*68 + f] = vv;
        }
        __syncthreads();

        // S = Q K^T   (rows ty*8+i, key-cols tx*4+j)
        float acc[8][4] = {};
        #pragma unroll 16
        for (int kk = 0; kk < 64; kk++) {
            float4 a0 = *(float4*)&Qs[kk*132 + ty*8];
            float4 a1 = *(float4*)&Qs[kk*132 + ty*8 + 4];
            float4 b0 = *(float4*)&Ks[kk*68 + tx*4];
            float ar[8] = {a0.x,a0.y,a0.z,a0.w,a1.x,a1.y,a1.z,a1.w};
            float br[4] = {b0.x,b0.y,b0.z,b0.w};
            #pragma unroll
            for (int i = 0; i < 8; i++)
                #pragma unroll
                for (int j = 0; j < 4; j++)
                    acc[i][j] = fmaf(ar[i], br[j], acc[i][j]);
        }

        // Mask + scale + online softmax (row group = 16 lanes sharing ty)
        #pragma unroll
        for (int i = 0; i < 8; i++) {
            const int q = q0 + ty*8 + i;
            float sv[4];
            float mx = -1e30f;
            #pragma unroll
            for (int j = 0; j < 4; j++) {
                int k = k0 + tx*4 + j;
                sv[j] = (k > q) ? acc[i][j] * 0.125f : -1e10f;
                mx = fmaxf(mx, sv[j]);
            }
            #pragma unroll
            for (int off = 8; off >= 1; off >>= 1)
                mx = fmaxf(mx, __shfl_xor_sync(0xffffffffu, mx, off));
            float m_new = fmaxf(m_i[i], mx);
            float a = __expf(m_i[i] - m_new);
            float s = 0.f;
            #pragma unroll
            for (int j = 0; j < 4; j++) { sv[j] = __expf(sv[j] - m_new); s += sv[j]; }
            #pragma unroll
            for (int off = 8; off >= 1; off >>= 1)
                s += __shfl_xor_sync(0xffffffffu, s, off);
            m_i[i] = m_new;
            l_i[i] = l_i[i] * a + s;
            #pragma unroll
            for (int j = 0; j < 4; j++) {
                O[i][j] *= a;
                Ps[(tx*4 + j)*132 + ty*8 + i] = sv[j];   // transposed store
            }
        }
        __syncthreads();

        // O += P @ V   (same register mapping: rows ty*8+i, h-cols tx*4+j)
        #pragma unroll 16
        for (int kk = 0; kk < 64; kk++) {
            float4 p0 = *(float4*)&Ps[kk*132 + ty*8];
            float4 p1 = *(float4*)&Ps[kk*132 + ty*8 + 4];
            float4 v0 = *(float4*)&Vs[kk*68 + tx*4];
            float pr[8] = {p0.x,p0.y,p0.z,p0.w,p1.x,p1.y,p1.z,p1.w};
            float vr[4] = {v0.x,v0.y,v0.z,v0.w};
            #pragma unroll
            for (int i = 0; i < 8; i++)
                #pragma unroll
                for (int j = 0; j < 4; j++)
                    O[i][j] = fmaf(pr[i], vr[j], O[i][j]);
        }
    }

    // Epilogue: z[b][q][n][h] = O / l
    const int b = bn >> 4, n = bn & 15;
    #pragma unroll
    for (int i = 0; i < 8; i++) {
        int q = q0 + ty*8 + i;
        float inv = 1.f / l_i[i];
        float* dst = &g_z[(((b*PP + q)*NHEAD + n)*HD) + tx*4];
        #pragma unroll
        for (int j = 0; j < 4; j++) dst[j] = O[i][j] * inv;
    }
}

// ---------------------------------------------------------------------------
// Fix-up: row q = P-1 is fully masked -> softmax of all -1e10 = uniform 1/P
// => z = mean_k v[k]
// ---------------------------------------------------------------------------
__global__ void fix_last_row()
{
    const int bn = blockIdx.x;
    const int h = threadIdx.x;
    const int b = bn >> 4, n = bn & 15;
    const float* v = &g_v[bn * PP * HD + h];
    float s = 0.f;
    for (int k = 0; k < PP; k++) s += v[k * HD];
    g_z[(((b*PP + (PP-1))*NHEAD + n)*HD) + h] = s * (1.0f / PP);
}

// ---------------------------------------------------------------------------
// Output projection: out[row, m] = sum_k z[row, k] * wo[k, m] + bias_out[m]
// z is contiguous [4096 x 1024]; wo [N,H,M] is contiguous [1024 x 1024].
// ---------------------------------------------------------------------------
__global__ __launch_bounds__(256) void oproj_kernel(
    const float* __restrict__ wo, const float* __restrict__ bias,
    float* __restrict__ out)
{
    __shared__ float As[16*132];
    __shared__ float Bs[16*68];

    const int c0 = blockIdx.x * 64;
    const int r0 = blockIdx.y * 128;
    const int tid = threadIdx.x;
    const int tx = tid & 15, ty = tid >> 4;

    float acc[8][4] = {};

    for (int k0 = 0; k0 < NHEAD*HD; k0 += 16) {
        #pragma unroll
        for (int t = 0; t < 2; t++) {
            int idx = tid + t*256;
            int r = idx >> 2, kc = (idx & 3) * 4;
            float4 v4 = *(const float4*)&g_z[(r0 + r)*(NHEAD*HD) + k0 + kc];
            As[(kc+0)*132 + r] = v4.x;
            As[(kc+1)*132 + r] = v4.y;
            As[(kc+2)*132 + r] = v4.z;
            As[(kc+3)*132 + r] = v4.w;
        }
        {
            int kr = tid >> 4, c4 = (tid & 15) * 4;
            *(float4*)&Bs[kr*68 + c4] = *(const float4*)&wo[(k0+kr)*MM + c0 + c4];
        }
        __syncthreads();
        #pragma unroll
        for (int kk = 0; kk < 16; kk++) {
            float4 a0 = *(float4*)&As[kk*132 + ty*8];
            float4 a1 = *(float4*)&As[kk*132 + ty*8 + 4];
            float4 b0 = *(float4*)&Bs[kk*68 + tx*4];
            float ar[8] = {a0.x,a0.y,a0.z,a0.w,a1.x,a1.y,a1.z,a1.w};
            float br[4] = {b0.x,b0.y,b0.z,b0.w};
            #pragma unroll
            for (int i = 0; i < 8; i++)
                #pragma unroll
                for (int j = 0; j < 4; j++)
                    acc[i][j] = fmaf(ar[i], br[j], acc[i][j]);
        }
        __syncthreads();
    }
    #pragma unroll
    for (int i = 0; i < 8; i++) {
        int r = r0 + ty*8 + i;
        float* dst = &out[r*MM + c0 + tx*4];
        #pragma unroll
        for (int j = 0; j < 4; j++)
            dst[j] = acc[i][j] + bias[c0 + tx*4 + j];
    }
}

// ---------------------------------------------------------------------------
extern "C" void kernel_launch(void* const* d_in, const int* in_sizes, int n_in,
                              void* d_out, int out_size)
{
    const float* x  = (const float*)d_in[0];
    const float* wq = (const float*)d_in[1];
    const float* wk = (const float*)d_in[2];
    const float* wv = (const float*)d_in[3];
    const float* wo = (const float*)d_in[4];
    const float* bq = (const float*)d_in[5];
    const float* bk = (const float*)d_in[6];
    const float* bv = (const float*)d_in[7];
    const float* bo = (const float*)d_in[8];
    float* out = (float*)d_out;

    const int smem_bytes = SM_FLOATS * (int)sizeof(float);   // 100 KB
    cudaFuncSetAttribute(attn_kernel,
                         cudaFuncAttributeMaxDynamicSharedMemorySize, smem_bytes);

    dim3 gemm_grid(NHEAD, (BB*PP)/128);   // (16, 32)
    qkv_kernel<0><<<gemm_grid, 256>>>(x, wq, bq);
    qkv_kernel<1><<<gemm_grid, 256>>>(x, wk, bk);
    qkv_kernel<2><<<gemm_grid, 256>>>(x, wv, bv);

    attn_kernel<<<dim3(PP/128, BB*NHEAD), 256, smem_bytes>>>();
    fix_last_row<<<BB*NHEAD, HD>>>();

    oproj_kernel<<<dim3(MM/64, (BB*PP)/128), 256>>>(wo, bo, out);
}

// round 5
// speedup vs baseline: 1.2506x; 1.2506x over previous
#include <cuda_runtime.h>
#include <cuda_bf16.h>
#include <math.h>
#include <stdint.h>

#define BB 2
#define PP 2048
#define MM 1024
#define NHEAD 16
#define HD 64

// Scratch (static device globals: allocation-guard safe)
__device__ float g_q[BB*NHEAD*PP*HD];   // [B,N,P,H]
__device__ float g_k[BB*NHEAD*PP*HD];
__device__ float g_v[BB*NHEAD*PP*HD];
__device__ float g_z[BB*PP*NHEAD*HD];   // [B,P,N,H]  (contiguous [4096 x 1024])

// ===========================================================================
// mma.sync (sm_80+ ISA, works on base sm_100 target) + ldmatrix helpers
// ===========================================================================
__device__ __forceinline__ uint32_t smem_u32(const void* p) {
    uint32_t a;
    asm("{ .reg .u64 t; cvta.to.shared.u64 t, %1; cvt.u32.u64 %0, t; }"
        : "=r"(a) : "l"(p));
    return a;
}
__device__ __forceinline__ void ldsm_x4(uint32_t* r, uint32_t addr) {
    asm volatile("ldmatrix.sync.aligned.m8n8.x4.shared.b16 {%0,%1,%2,%3}, [%4];"
        : "=r"(r[0]), "=r"(r[1]), "=r"(r[2]), "=r"(r[3]) : "r"(addr));
}
__device__ __forceinline__ void ldsm_x4_t(uint32_t* r, uint32_t addr) {
    asm volatile("ldmatrix.sync.aligned.m8n8.x4.trans.shared.b16 {%0,%1,%2,%3}, [%4];"
        : "=r"(r[0]), "=r"(r[1]), "=r"(r[2]), "=r"(r[3]) : "r"(addr));
}
__device__ __forceinline__ void mma_bf16(float* d, const uint32_t* a, const uint32_t* b) {
    asm volatile("mma.sync.aligned.m16n8k16.row.col.f32.bf16.bf16.f32 "
        "{%0,%1,%2,%3}, {%4,%5,%6,%7}, {%8,%9}, {%0,%1,%2,%3};"
        : "+f"(d[0]), "+f"(d[1]), "+f"(d[2]), "+f"(d[3])
        : "r"(a[0]), "r"(a[1]), "r"(a[2]), "r"(a[3]), "r"(b[0]), "r"(b[1]));
}

// bf16 hi/lo split + pack of two adjacent elements (along the packed axis)
__device__ __forceinline__ void split2(float a, float b, uint32_t& hi2, uint32_t& lo2) {
    __nv_bfloat16 ah = __float2bfloat16(a), bh = __float2bfloat16(b);
    float ar = a - __bfloat162float(ah), br = b - __bfloat162float(bh);
    __nv_bfloat162 h; h.x = ah; h.y = bh;
    __nv_bfloat162 l; l.x = __float2bfloat16(ar); l.y = __float2bfloat16(br);
    hi2 = *(uint32_t*)&h; lo2 = *(uint32_t*)&l;
}

// ===========================================================================
// Shared 128x64-tile GEMM mainloop on HMMA (bf16 hi/lo split).
// A: row-major [row][k] (k contiguous).  B: row-major [k][n] (n contiguous).
// 256 threads = 8 warps; warp w computes rows w*16..w*16+15 x all 64 n.
// ===========================================================================
#define PA_U32 20      // A smem pitch: 40 bf16 = 80 B (rows conflict-free for ldmatrix)
#define PB_U32 36      // B smem pitch: 72 bf16 = 144 B (rows conflict-free)

struct GemmSmem {
    uint32_t Ah[128*PA_U32];
    uint32_t Al[128*PA_U32];
    uint32_t Bh[32*PB_U32];
    uint32_t Bl[32*PB_U32];
};

__device__ __forceinline__ void gemm128x64(
    const float* __restrict__ A0, int lda,
    const float* __restrict__ B0, int ldb,
    int K, GemmSmem* sm, float acc[8][4])
{
    const int tid = threadIdx.x;
    const int wid = tid >> 5, l = tid & 31;
    const int wr = wid * 16;
    const uint32_t ah_b = smem_u32(sm->Ah);
    const uint32_t al_b = smem_u32(sm->Al);
    const uint32_t bh_b = smem_u32(sm->Bh);
    const uint32_t bl_b = smem_u32(sm->Bl);

    // ldmatrix per-lane address components
    const int arow = wr + (l & 15);               // A: rows wr..wr+15 (x2 groups)
    const int akb  = (l >> 4) * 16;               // A: +8 bf16 (16 B) for k8-15 group
    const int brow = (l & 7) + ((l >> 3) & 1) * 8;// B: k-row within kstep
    const int bnb  = (l >> 4) * 16;               // B: +8 n (16 B) for 2nd n-tile

    for (int k0 = 0; k0 < K; k0 += 32) {
        // ---- stage A tile: 128 rows x 16 k-pairs (hi/lo) ----
        #pragma unroll
        for (int t = 0; t < 8; t++) {
            int idx = t*256 + tid;
            int row = idx >> 4, kp = idx & 15;
            float2 v = *(const float2*)&A0[row*lda + k0 + kp*2];
            uint32_t h2, l2; split2(v.x, v.y, h2, l2);
            sm->Ah[row*PA_U32 + kp] = h2;
            sm->Al[row*PA_U32 + kp] = l2;
        }
        // ---- stage B tile: 32 k rows x 32 n-pairs (coalesced in n) ----
        #pragma unroll
        for (int t = 0; t < 4; t++) {
            int idx = t*256 + tid;
            int kk = idx >> 5, np = idx & 31;
            float2 v = *(const float2*)&B0[(size_t)(k0+kk)*ldb + np*2];
            uint32_t h2, l2; split2(v.x, v.y, h2, l2);
            sm->Bh[kk*PB_U32 + np] = h2;
            sm->Bl[kk*PB_U32 + np] = l2;
        }
        __syncthreads();

        #pragma unroll
        for (int ks = 0; ks < 2; ks++) {
            uint32_t ah[4], al[4];
            uint32_t a_off = (uint32_t)(arow*80 + ks*32 + akb);
            ldsm_x4(ah, ah_b + a_off);
            ldsm_x4(al, al_b + a_off);
            #pragma unroll
            for (int nt2 = 0; nt2 < 4; nt2++) {
                uint32_t bh[4], bl[4];
                uint32_t b_off = (uint32_t)((ks*16 + brow)*144 + nt2*32 + bnb);
                ldsm_x4_t(bh, bh_b + b_off);
                ldsm_x4_t(bl, bl_b + b_off);
                mma_bf16(acc[nt2*2+0], ah, bh);      // hi*hi
                mma_bf16(acc[nt2*2+1], ah, bh+2);
                mma_bf16(acc[nt2*2+0], ah, bl);      // hi*lo
                mma_bf16(acc[nt2*2+1], ah, bl+2);
                mma_bf16(acc[nt2*2+0], al, bh);      // lo*hi
                mma_bf16(acc[nt2*2+1], al, bh+2);
            }
        }
        __syncthreads();
    }
}

// ===========================================================================
// QKV projection: dst[b,n,p,h] = sum_m x[b,p,m] * w[n,m,h] + bias[n,h]
// grid (NHEAD, 32 row-tiles); DST selects g_q/g_k/g_v.
// ===========================================================================
template<int DST>
__global__ __launch_bounds__(256) void qkv_mma(
    const float* __restrict__ x, const float* __restrict__ w,
    const float* __restrict__ bias)
{
    __shared__ GemmSmem sm;
    const int head = blockIdx.x;
    const int r0 = blockIdx.y * 128;
    float acc[8][4] = {};
    gemm128x64(x + (size_t)r0*MM, MM, w + (size_t)head*MM*HD, HD, MM, &sm, acc);

    const int tid = threadIdx.x, wid = tid>>5, l = tid&31;
    float* outp = (DST == 0) ? g_q : (DST == 1) ? g_k : g_v;
    const int rowa = r0 + wid*16 + (l>>2);
    const int col  = (l&3)*2;
    #pragma unroll
    for (int nt = 0; nt < 8; nt++) {
        int c = nt*8 + col;
        float2 b2 = *(const float2*)&bias[head*HD + c];
        int r1 = rowa, r2 = rowa + 8;
        int b1_ = r1 >> 11, p1 = r1 & (PP-1);
        int b2_ = r2 >> 11, p2 = r2 & (PP-1);
        *(float2*)&outp[((size_t)(b1_*NHEAD + head)*PP + p1)*HD + c] =
            make_float2(acc[nt][0] + b2.x, acc[nt][1] + b2.y);
        *(float2*)&outp[((size_t)(b2_*NHEAD + head)*PP + p2)*HD + c] =
            make_float2(acc[nt][2] + b2.x, acc[nt][3] + b2.y);
    }
}

// ===========================================================================
// Output projection: out[row,m] = sum_k z[row,k]*wo[k,m] + bias[m]
// grid (MM/64, 32 row-tiles).
// ===========================================================================
__global__ __launch_bounds__(256) void oproj_mma(
    const float* __restrict__ wo, const float* __restrict__ bias,
    float* __restrict__ out)
{
    __shared__ GemmSmem sm;
    const int c0 = blockIdx.x * 64;
    const int r0 = blockIdx.y * 128;
    float acc[8][4] = {};
    gemm128x64(g_z + (size_t)r0*MM, MM, wo + c0, MM, MM, &sm, acc);

    const int tid = threadIdx.x, wid = tid>>5, l = tid&31;
    const int rowa = r0 + wid*16 + (l>>2);
    const int col  = (l&3)*2;
    #pragma unroll
    for (int nt = 0; nt < 8; nt++) {
        int c = c0 + nt*8 + col;
        float2 b2 = *(const float2*)&bias[c];
        *(float2*)&out[(size_t)rowa*MM + c] =
            make_float2(acc[nt][0] + b2.x, acc[nt][1] + b2.y);
        *(float2*)&out[(size_t)(rowa+8)*MM + c] =
            make_float2(acc[nt][2] + b2.x, acc[nt][3] + b2.y);
    }
}

// ===========================================================================
// Fused attention (SIMT fp32); Ps row-major (conflict-free STS + broadcast LDS).
// Mask keeps STRICTLY-UPPER triangle (k > q); masked entries exactly -1e10.
// ===========================================================================
#define SMQ 0                       // Qs_t [64][132]  (feature-major)
#define SMK (64*132)                // Ks_t [64][68]   (feature-major)
#define SMV (SMK + 64*68)           // Vs   [64][68]   (key-major)
#define SMP (SMV + 64*68)           // Ps   [128][68]  (row-major)
#define SM_FLOATS (SMP + 128*68)    // 25856 floats = 103424 B

extern __shared__ unsigned char dynsmem[];

__global__ __launch_bounds__(256, 2) void attn_kernel()
{
    float* smf = (float*)dynsmem;
    const int q0 = blockIdx.x * 128;
    const int bn = blockIdx.y;          // b*NHEAD + n
    const int base = bn * PP * HD;
    const int tid = threadIdx.x;
    const int tx = tid & 15, ty = tid >> 4;

    float* Qs = smf + SMQ;
    float* Ks = smf + SMK;
    float* Vs = smf + SMV;
    float* Ps = smf + SMP;

    #pragma unroll
    for (int t = 0; t < 8; t++) {
        int idx = tid + t*256;
        int r = idx >> 4, f = (idx & 15) * 4;
        float4 v4 = *(const float4*)&g_q[base + (q0 + r)*HD + f];
        Qs[(f+0)*132 + r] = v4.x;
        Qs[(f+1)*132 + r] = v4.y;
        Qs[(f+2)*132 + r] = v4.z;
        Qs[(f+3)*132 + r] = v4.w;
    }

    float m_i[8], l_i[8], O[8][4];
    #pragma unroll
    for (int i = 0; i < 8; i++) {
        m_i[i] = -1e30f; l_i[i] = 0.f;
        #pragma unroll
        for (int j = 0; j < 4; j++) O[i][j] = 0.f;
    }

    // Tiles fully below q0 contribute exactly 0 (underflowed exp) for every
    // row except the fully-masked q=P-1 (fixed by fix_last_row).
    for (int k0 = q0; k0 < PP; k0 += 64) {
        __syncthreads();
        #pragma unroll
        for (int t = 0; t < 4; t++) {
            int idx = tid + t*256;
            int c = idx >> 4, f = (idx & 15) * 4;
            float4 kv = *(const float4*)&g_k[base + (k0 + c)*HD + f];
            Ks[(f+0)*68 + c] = kv.x;
            Ks[(f+1)*68 + c] = kv.y;
            Ks[(f+2)*68 + c] = kv.z;
            Ks[(f+3)*68 + c] = kv.w;
            float4 vv = *(const float4*)&g_v[base + (k0 + c)*HD + f];
            *(float4*)&Vs[c*68 + f] = vv;
        }
        __syncthreads();

        float acc[8][4] = {};
        #pragma unroll 16
        for (int kk = 0; kk < 64; kk++) {
            float4 a0 = *(float4*)&Qs[kk*132 + ty*8];
            float4 a1 = *(float4*)&Qs[kk*132 + ty*8 + 4];
            float4 b0 = *(float4*)&Ks[kk*68 + tx*4];
            float ar[8] = {a0.x,a0.y,a0.z,a0.w,a1.x,a1.y,a1.z,a1.w};
            float br[4] = {b0.x,b0.y,b0.z,b0.w};
            #pragma unroll
            for (int i = 0; i < 8; i++)
                #pragma unroll
                for (int j = 0; j < 4; j++)
                    acc[i][j] = fmaf(ar[i], br[j], acc[i][j]);
        }

        #pragma unroll
        for (int i = 0; i < 8; i++) {
            const int q = q0 + ty*8 + i;
            float sv[4];
            float mx = -1e30f;
            #pragma unroll
            for (int j = 0; j < 4; j++) {
                int k = k0 + tx*4 + j;
                sv[j] = (k > q) ? acc[i][j] * 0.125f : -1e10f;
                mx = fmaxf(mx, sv[j]);
            }
            #pragma unroll
            for (int off = 8; off >= 1; off >>= 1)
                mx = fmaxf(mx, __shfl_xor_sync(0xffffffffu, mx, off));
            float m_new = fmaxf(m_i[i], mx);
            float a = __expf(m_i[i] - m_new);
            float s = 0.f;
            #pragma unroll
            for (int j = 0; j < 4; j++) { sv[j] = __expf(sv[j] - m_new); s += sv[j]; }
            #pragma unroll
            for (int off = 8; off >= 1; off >>= 1)
                s += __shfl_xor_sync(0xffffffffu, s, off);
            m_i[i] = m_new;
            l_i[i] = l_i[i] * a + s;
            #pragma unroll
            for (int j = 0; j < 4; j++) O[i][j] *= a;
            *(float4*)&Ps[(ty*8 + i)*68 + tx*4] = make_float4(sv[0], sv[1], sv[2], sv[3]);
        }
        __syncthreads();

        // O += P @ V  (P broadcast per 16-lane row-group; conflict-free)
        #pragma unroll 4
        for (int kk0 = 0; kk0 < 64; kk0 += 4) {
            float4 v0 = *(float4*)&Vs[(kk0+0)*68 + tx*4];
            float4 v1 = *(float4*)&Vs[(kk0+1)*68 + tx*4];
            float4 v2 = *(float4*)&Vs[(kk0+2)*68 + tx*4];
            float4 v3 = *(float4*)&Vs[(kk0+3)*68 + tx*4];
            #pragma unroll
            for (int i = 0; i < 8; i++) {
                float4 p = *(float4*)&Ps[(ty*8 + i)*68 + kk0];
                O[i][0] = fmaf(p.x, v0.x, O[i][0]);
                O[i][1] = fmaf(p.x, v0.y, O[i][1]);
                O[i][2] = fmaf(p.x, v0.z, O[i][2]);
                O[i][3] = fmaf(p.x, v0.w, O[i][3]);
                O[i][0] = fmaf(p.y, v1.x, O[i][0]);
                O[i][1] = fmaf(p.y, v1.y, O[i][1]);
                O[i][2] = fmaf(p.y, v1.z, O[i][2]);
                O[i][3] = fmaf(p.y, v1.w, O[i][3]);
                O[i][0] = fmaf(p.z, v2.x, O[i][0]);
                O[i][1] = fmaf(p.z, v2.y, O[i][1]);
                O[i][2] = fmaf(p.z, v2.z, O[i][2]);
                O[i][3] = fmaf(p.z, v2.w, O[i][3]);
                O[i][0] = fmaf(p.w, v3.x, O[i][0]);
                O[i][1] = fmaf(p.w, v3.y, O[i][1]);
                O[i][2] = fmaf(p.w, v3.z, O[i][2]);
                O[i][3] = fmaf(p.w, v3.w, O[i][3]);
            }
        }
    }

    const int b = bn >> 4, n = bn & 15;
    #pragma unroll
    for (int i = 0; i < 8; i++) {
        int q = q0 + ty*8 + i;
        float inv = 1.f / l_i[i];
        float* dst = &g_z[(((b*PP + q)*NHEAD + n)*HD) + tx*4];
        #pragma unroll
        for (int j = 0; j < 4; j++) dst[j] = O[i][j] * inv;
    }
}

// ---------------------------------------------------------------------------
// Fix-up: row q = P-1 fully masked -> uniform pattern -> z = mean_k v[k]
// ---------------------------------------------------------------------------
__global__ void fix_last_row()
{
    const int bn = blockIdx.x;
    const int h = threadIdx.x;
    const int b = bn >> 4, n = bn & 15;
    const float* v = &g_v[bn * PP * HD + h];
    float s = 0.f;
    for (int k = 0; k < PP; k++) s += v[k * HD];
    g_z[(((b*PP + (PP-1))*NHEAD + n)*HD) + h] = s * (1.0f / PP);
}

// ---------------------------------------------------------------------------
extern "C" void kernel_launch(void* const* d_in, const int* in_sizes, int n_in,
                              void* d_out, int out_size)
{
    const float* x  = (const float*)d_in[0];
    const float* wq = (const float*)d_in[1];
    const float* wk = (const float*)d_in[2];
    const float* wv = (const float*)d_in[3];
    const float* wo = (const float*)d_in[4];
    const float* bq = (const float*)d_in[5];
    const float* bk = (const float*)d_in[6];
    const float* bv = (const float*)d_in[7];
    const float* bo = (const float*)d_in[8];
    float* out = (float*)d_out;

    cudaFuncSetAttribute(attn_kernel, cudaFuncAttributeMaxDynamicSharedMemorySize,
                         SM_FLOATS * (int)sizeof(float));

    dim3 gemm_grid(NHEAD, (BB*PP)/128);   // (16, 32)
    qkv_mma<0><<<gemm_grid, 256>>>(x, wq, bq);
    qkv_mma<1><<<gemm_grid, 256>>>(x, wk, bk);
    qkv_mma<2><<<gemm_grid, 256>>>(x, wv, bv);

    attn_kernel<<<dim3(PP/128, BB*NHEAD), 256, SM_FLOATS * sizeof(float)>>>();
    fix_last_row<<<BB*NHEAD, HD>>>();

    oproj_mma<<<dim3(MM/64, (BB*PP)/128), 256>>>(wo, bo, out);
}

// round 11
// speedup vs baseline: 1.7812x; 1.4243x over previous
#include <cuda_runtime.h>
#include <cuda_bf16.h>
#include <stdint.h>

#define BB 2
#define PP 2048
#define MM 1024
#define NHEAD 16
#define HD 64

// Scratch: EXACT round-5 configuration (passed, delta=0): 64 MB fp32.
__device__ float g_q[BB*NHEAD*PP*HD];   // [B,N,P,H]
__device__ float g_k[BB*NHEAD*PP*HD];
__device__ float g_v[BB*NHEAD*PP*HD];
__device__ float g_z[BB*PP*MM];         // [B,P,N,H]

// ---------------------------------------------------------------------------
// helpers (identical to round-5 passing kernel)
// ---------------------------------------------------------------------------
__device__ __forceinline__ uint32_t smem_u32(const void* p) {
    uint32_t a;
    asm("{ .reg .u64 t; cvta.to.shared.u64 t, %1; cvt.u32.u64 %0, t; }"
        : "=r"(a) : "l"(p));
    return a;
}
__device__ __forceinline__ void ldsm_x4(uint32_t* r, uint32_t addr) {
    asm volatile("ldmatrix.sync.aligned.m8n8.x4.shared.b16 {%0,%1,%2,%3}, [%4];"
        : "=r"(r[0]), "=r"(r[1]), "=r"(r[2]), "=r"(r[3]) : "r"(addr));
}
__device__ __forceinline__ void ldsm_x4_t(uint32_t* r, uint32_t addr) {
    asm volatile("ldmatrix.sync.aligned.m8n8.x4.trans.shared.b16 {%0,%1,%2,%3}, [%4];"
        : "=r"(r[0]), "=r"(r[1]), "=r"(r[2]), "=r"(r[3]) : "r"(addr));
}
__device__ __forceinline__ void mma_bf16(float* d, const uint32_t* a, const uint32_t* b) {
    asm volatile("mma.sync.aligned.m16n8k16.row.col.f32.bf16.bf16.f32 "
        "{%0,%1,%2,%3}, {%4,%5,%6,%7}, {%8,%9}, {%0,%1,%2,%3};"
        : "+f"(d[0]), "+f"(d[1]), "+f"(d[2]), "+f"(d[3])
        : "r"(a[0]), "r"(a[1]), "r"(a[2]), "r"(a[3]), "r"(b[0]), "r"(b[1]));
}
// scalar-B variant: NO intermediate arrays (suspected lmem trigger removed)
__device__ __forceinline__ void mma_bf16_s(float* d, const uint32_t* a,
                                           uint32_t b0, uint32_t b1) {
    asm volatile("mma.sync.aligned.m16n8k16.row.col.f32.bf16.bf16.f32 "
        "{%0,%1,%2,%3}, {%4,%5,%6,%7}, {%8,%9}, {%0,%1,%2,%3};"
        : "+f"(d[0]), "+f"(d[1]), "+f"(d[2]), "+f"(d[3])
        : "r"(a[0]), "r"(a[1]), "r"(a[2]), "r"(a[3]), "r"(b0), "r"(b1));
}
__device__ __forceinline__ void split2(float a, float b, uint32_t& hi2, uint32_t& lo2) {
    __nv_bfloat16 ah = __float2bfloat16(a), bh = __float2bfloat16(b);
    float ar = a - __bfloat162float(ah), br = b - __bfloat162float(bh);
    __nv_bfloat162 h; h.x = ah; h.y = bh;
    __nv_bfloat162 l; l.x = __float2bfloat16(ar); l.y = __float2bfloat16(br);
    hi2 = *(uint32_t*)&h; lo2 = *(uint32_t*)&l;
}

// ---------------------------------------------------------------------------
// 128x64-tile GEMM mainloop (ROUND-5 VERBATIM — passed, delta=0).
// A: row-major fp32 [row][k].  B: row-major fp32 [k][n].
// ---------------------------------------------------------------------------
#define PA_U32 20      // A smem pitch: 80 B
#define PB_U32 36      // B smem pitch: 144 B

struct GemmSmem {
    uint32_t Ah[128*PA_U32];
    uint32_t Al[128*PA_U32];
    uint32_t Bh[32*PB_U32];
    uint32_t Bl[32*PB_U32];
};

__device__ __forceinline__ void gemm128x64(
    const float* __restrict__ A0, int lda,
    const float* __restrict__ B0, int ldb,
    int K, GemmSmem* sm, float acc[8][4])
{
    const int tid = threadIdx.x;
    const int wid = tid >> 5, l = tid & 31;
    const uint32_t ah_b = smem_u32(sm->Ah);
    const uint32_t al_b = smem_u32(sm->Al);
    const uint32_t bh_b = smem_u32(sm->Bh);
    const uint32_t bl_b = smem_u32(sm->Bl);

    const int arow = wid*16 + (l & 15);
    const int akb  = (l >> 4) * 16;
    const int brow = (l & 7) + ((l >> 3) & 1) * 8;
    const int bnb  = (l >> 4) * 16;

    for (int k0 = 0; k0 < K; k0 += 32) {
        #pragma unroll
        for (int t = 0; t < 8; t++) {
            int idx = t*256 + tid;
            int row = idx >> 4, kp = idx & 15;
            float2 v = *(const float2*)&A0[(size_t)row*lda + k0 + kp*2];
            uint32_t h2, l2; split2(v.x, v.y, h2, l2);
            sm->Ah[row*PA_U32 + kp] = h2;
            sm->Al[row*PA_U32 + kp] = l2;
        }
        #pragma unroll
        for (int t = 0; t < 4; t++) {
            int idx = t*256 + tid;
            int kk = idx >> 5, np = idx & 31;
            float2 v = *(const float2*)&B0[(size_t)(k0+kk)*ldb + np*2];
            uint32_t h2, l2; split2(v.x, v.y, h2, l2);
            sm->Bh[kk*PB_U32 + np] = h2;
            sm->Bl[kk*PB_U32 + np] = l2;
        }
        __syncthreads();

        #pragma unroll
        for (int ks = 0; ks < 2; ks++) {
            uint32_t ah[4], al[4];
            uint32_t a_off = (uint32_t)(arow*80 + ks*32 + akb);
            ldsm_x4(ah, ah_b + a_off);
            ldsm_x4(al, al_b + a_off);
            #pragma unroll
            for (int nt2 = 0; nt2 < 4; nt2++) {
                uint32_t bh[4], bl[4];
                uint32_t b_off = (uint32_t)((ks*16 + brow)*144 + nt2*32 + bnb);
                ldsm_x4_t(bh, bh_b + b_off);
                ldsm_x4_t(bl, bl_b + b_off);
                mma_bf16(acc[nt2*2+0], ah, bh);
                mma_bf16(acc[nt2*2+1], ah, bh+2);
                mma_bf16(acc[nt2*2+0], ah, bl);
                mma_bf16(acc[nt2*2+1], ah, bl+2);
                mma_bf16(acc[nt2*2+0], al, bh);
                mma_bf16(acc[nt2*2+1], al, bh+2);
            }
        }
        __syncthreads();
    }
}

// ---------------------------------------------------------------------------
// QKV projection (ROUND-5 VERBATIM): fp32 x, fp32 w -> fp32 q/k/v [B,N,P,H]
// ---------------------------------------------------------------------------
template<int DST>
__global__ __launch_bounds__(256) void qkv_mma(
    const float* __restrict__ x, const float* __restrict__ w,
    const float* __restrict__ bias)
{
    __shared__ GemmSmem sm;
    const int head = blockIdx.x;
    const int r0 = blockIdx.y * 128;
    float acc[8][4] = {};
    gemm128x64(x + (size_t)r0*MM, MM, w + (size_t)head*MM*HD, HD, MM, &sm, acc);

    const int tid = threadIdx.x, wid = tid>>5, l = tid&31;
    float* outp = (DST == 0) ? g_q : (DST == 1) ? g_k : g_v;
    const int rowa = r0 + wid*16 + (l>>2);
    const int col  = (l&3)*2;
    #pragma unroll
    for (int nt = 0; nt < 8; nt++) {
        int c = nt*8 + col;
        float2 b2 = *(const float2*)&bias[head*HD + c];
        int r1 = rowa, r2 = rowa + 8;
        int b1_ = r1 >> 11, p1 = r1 & (PP-1);
        int b2_ = r2 >> 11, p2 = r2 & (PP-1);
        *(float2*)&outp[((size_t)(b1_*NHEAD + head)*PP + p1)*HD + c] =
            make_float2(acc[nt][0] + b2.x, acc[nt][1] + b2.y);
        *(float2*)&outp[((size_t)(b2_*NHEAD + head)*PP + p2)*HD + c] =
            make_float2(acc[nt][2] + b2.x, acc[nt][3] + b2.y);
    }
}

// ---------------------------------------------------------------------------
// Tensor-core flash attention, scalar-B mma (no array-copy inits anywhere).
// fp32 q/k/v in, fp32 z out. Mask keeps k > q; masked = -1e10.
// Low pressure: 32-key halves, Q frags reloaded, P via smem.
// ---------------------------------------------------------------------------
#define AT_P32 36      // 72 bf16 per row = 144 B pitch

struct AttnSmem {
    uint32_t Qh[128*AT_P32], Ql[128*AT_P32];
    uint32_t Kh[64*AT_P32],  Kl[64*AT_P32];
    uint32_t Vh[64*AT_P32],  Vl[64*AT_P32];
    uint32_t Ph[128*AT_P32], Pl[128*AT_P32];
};  // 110592 B

extern __shared__ unsigned char dynsmem[];

__global__ __launch_bounds__(256) void attn_mma()
{
    AttnSmem* sm = (AttnSmem*)dynsmem;
    const int q0 = blockIdx.x * 128;
    const int bn = blockIdx.y;
    const size_t base = (size_t)bn * PP * HD;
    const int tid = threadIdx.x;
    const int w = tid >> 5, l = tid & 31;
    const int gid = l >> 2, tid4 = l & 3;

    // Stage Q tile: fp32 -> bf16 hi/lo (split2: proven pattern)
    #pragma unroll
    for (int t = 0; t < 16; t++) {
        int idx = t*256 + tid;
        int row = idx >> 5, kp = idx & 31;
        float2 v = *(const float2*)&g_q[base + (size_t)(q0+row)*HD + kp*2];
        uint32_t h2, l2; split2(v.x, v.y, h2, l2);
        sm->Qh[row*AT_P32 + kp] = h2;
        sm->Ql[row*AT_P32 + kp] = l2;
    }
    __syncthreads();

    float O[8][4];
    #pragma unroll
    for (int i = 0; i < 8; i++) O[i][0]=O[i][1]=O[i][2]=O[i][3]=0.f;
    float m0 = -1e30f, m1 = -1e30f, l0 = 0.f, l1 = 0.f;
    const int row0 = q0 + w*16 + gid, row1 = row0 + 8;

    const uint32_t qh_b = smem_u32(sm->Qh), ql_b = smem_u32(sm->Ql);
    const uint32_t kh_b = smem_u32(sm->Kh), kl_b = smem_u32(sm->Kl);
    const uint32_t vh_b = smem_u32(sm->Vh), vl_b = smem_u32(sm->Vl);
    const uint32_t ph_b = smem_u32(sm->Ph), pl_b = smem_u32(sm->Pl);
    const uint32_t qoff = (uint32_t)(((w*16 + (l&15))*72 + (l>>4)*8) * 2);
    const uint32_t koff = (uint32_t)(((l&15)*72 + (l>>4)*8) * 2);
    const int vrow = (l&7) + ((l>>3)&1)*8;
    const uint32_t voff = (uint32_t)((vrow*72 + (l>>4)*8) * 2);
    const int prow0 = w*16 + gid;

    for (int k0 = q0; k0 < PP; k0 += 64) {
        __syncthreads();
        // Stage K/V tiles: fp32 -> bf16 hi/lo
        #pragma unroll
        for (int t = 0; t < 8; t++) {
            int idx = t*256 + tid;
            int row = idx >> 5, kp = idx & 31;
            float2 kv = *(const float2*)&g_k[base + (size_t)(k0+row)*HD + kp*2];
            uint32_t h2, l2; split2(kv.x, kv.y, h2, l2);
            sm->Kh[row*AT_P32+kp] = h2;
            sm->Kl[row*AT_P32+kp] = l2;
            float2 vv = *(const float2*)&g_v[base + (size_t)(k0+row)*HD + kp*2];
            split2(vv.x, vv.y, h2, l2);
            sm->Vh[row*AT_P32+kp] = h2;
            sm->Vl[row*AT_P32+kp] = l2;
        }
        __syncthreads();

        #pragma unroll
        for (int h2i = 0; h2i < 2; h2i++) {
            // ---- S = Q K^T over 32 keys (3-term split; scalar-B mma) ----
            float S[4][4];
            #pragma unroll
            for (int i = 0; i < 4; i++) S[i][0]=S[i][1]=S[i][2]=S[i][3]=0.f;
            #pragma unroll
            for (int kf = 0; kf < 4; kf++) {
                uint32_t qh4[4], ql4[4];
                ldsm_x4(qh4, qh_b + qoff + kf*32);
                ldsm_x4(ql4, ql_b + qoff + kf*32);
                #pragma unroll
                for (int kt = 0; kt < 2; kt++) {
                    uint32_t o2 = koff + (uint32_t)((h2i*32 + kt*16)*144 + kf*32);
                    uint32_t kh4[4], kl4[4];
                    ldsm_x4(kh4, kh_b + o2);
                    ldsm_x4(kl4, kl_b + o2);
                    mma_bf16_s(S[2*kt],   qh4, kh4[0], kh4[2]);
                    mma_bf16_s(S[2*kt+1], qh4, kh4[1], kh4[3]);
                    mma_bf16_s(S[2*kt],   qh4, kl4[0], kl4[2]);
                    mma_bf16_s(S[2*kt+1], qh4, kl4[1], kl4[3]);
                    mma_bf16_s(S[2*kt],   ql4, kh4[0], kh4[2]);
                    mma_bf16_s(S[2*kt+1], ql4, kh4[1], kh4[3]);
                }
            }

            // ---- mask + scale ----
            #pragma unroll
            for (int nt = 0; nt < 4; nt++) {
                int kb = k0 + h2i*32 + nt*8 + tid4*2;
                S[nt][0] = (kb   > row0) ? S[nt][0]*0.125f : -1e10f;
                S[nt][1] = (kb+1 > row0) ? S[nt][1]*0.125f : -1e10f;
                S[nt][2] = (kb   > row1) ? S[nt][2]*0.125f : -1e10f;
                S[nt][3] = (kb+1 > row1) ? S[nt][3]*0.125f : -1e10f;
            }
            // ---- row max (quad shfl) ----
            float mx0 = -1e30f, mx1 = -1e30f;
            #pragma unroll
            for (int nt = 0; nt < 4; nt++) {
                mx0 = fmaxf(mx0, fmaxf(S[nt][0], S[nt][1]));
                mx1 = fmaxf(mx1, fmaxf(S[nt][2], S[nt][3]));
            }
            mx0 = fmaxf(mx0, __shfl_xor_sync(0xffffffffu, mx0, 1));
            mx0 = fmaxf(mx0, __shfl_xor_sync(0xffffffffu, mx0, 2));
            mx1 = fmaxf(mx1, __shfl_xor_sync(0xffffffffu, mx1, 1));
            mx1 = fmaxf(mx1, __shfl_xor_sync(0xffffffffu, mx1, 2));
            float mn0 = fmaxf(m0, mx0), mn1 = fmaxf(m1, mx1);
            float a0 = __expf(m0 - mn0), a1 = __expf(m1 - mn1);

            // ---- exp + sums; P -> smem bf16 hi/lo ----
            float s0 = 0.f, s1 = 0.f;
            #pragma unroll
            for (int nt = 0; nt < 4; nt++) {
                float p0 = __expf(S[nt][0] - mn0);
                float p1 = __expf(S[nt][1] - mn0);
                float p2 = __expf(S[nt][2] - mn1);
                float p3 = __expf(S[nt][3] - mn1);
                s0 += p0 + p1;
                s1 += p2 + p3;
                uint32_t hh2, ll2;
                split2(p0, p1, hh2, ll2);
                sm->Ph[prow0*AT_P32 + h2i*16 + nt*4 + tid4] = hh2;
                sm->Pl[prow0*AT_P32 + h2i*16 + nt*4 + tid4] = ll2;
                split2(p2, p3, hh2, ll2);
                sm->Ph[(prow0+8)*AT_P32 + h2i*16 + nt*4 + tid4] = hh2;
                sm->Pl[(prow0+8)*AT_P32 + h2i*16 + nt*4 + tid4] = ll2;
            }
            s0 += __shfl_xor_sync(0xffffffffu, s0, 1);
            s0 += __shfl_xor_sync(0xffffffffu, s0, 2);
            s1 += __shfl_xor_sync(0xffffffffu, s1, 1);
            s1 += __shfl_xor_sync(0xffffffffu, s1, 2);
            l0 = l0*a0 + s0;  l1 = l1*a1 + s1;
            m0 = mn0;  m1 = mn1;
            #pragma unroll
            for (int ht = 0; ht < 8; ht++) {
                O[ht][0] *= a0; O[ht][1] *= a0;
                O[ht][2] *= a1; O[ht][3] *= a1;
            }
            __syncwarp();   // this warp's P rows written only by this warp

            // ---- O += P V for this 32-key half (3-term; scalar-B mma) ----
            #pragma unroll
            for (int kkf = 0; kkf < 2; kkf++) {
                int g = h2i*2 + kkf;
                uint32_t pf_h[4], pf_l[4];
                ldsm_x4(pf_h, ph_b + qoff + g*32);
                ldsm_x4(pf_l, pl_b + qoff + g*32);
                #pragma unroll
                for (int hf = 0; hf < 4; hf++) {
                    uint32_t vh4[4], vl4[4];
                    uint32_t o2 = voff + (uint32_t)(g*16*144 + hf*32);
                    ldsm_x4_t(vh4, vh_b + o2);
                    ldsm_x4_t(vl4, vl_b + o2);
                    mma_bf16_s(O[2*hf],   pf_h, vh4[0], vh4[1]);
                    mma_bf16_s(O[2*hf+1], pf_h, vh4[2], vh4[3]);
                    mma_bf16_s(O[2*hf],   pf_h, vl4[0], vl4[1]);
                    mma_bf16_s(O[2*hf+1], pf_h, vl4[2], vl4[3]);
                    mma_bf16_s(O[2*hf],   pf_l, vh4[0], vh4[1]);
                    mma_bf16_s(O[2*hf+1], pf_l, vh4[2], vh4[3]);
                }
            }
        }
    }

    // ---- epilogue: z = O / l -> fp32 [B,P,N,H] ----
    const int b = bn >> 4, n = bn & 15;
    const float inv0 = 1.f / l0, inv1 = 1.f / l1;
    #pragma unroll
    for (int ht = 0; ht < 8; ht++) {
        int h = ht*8 + tid4*2;
        *(float2*)&g_z[((size_t)(b*PP + row0)*NHEAD + n)*HD + h] =
            make_float2(O[ht][0]*inv0, O[ht][1]*inv0);
        *(float2*)&g_z[((size_t)(b*PP + row1)*NHEAD + n)*HD + h] =
            make_float2(O[ht][2]*inv1, O[ht][3]*inv1);
    }
}

// ---------------------------------------------------------------------------
// Fix-up (ROUND-5 VERBATIM): row q = P-1 fully masked -> z = mean_k v[k]
// ---------------------------------------------------------------------------
__global__ void fix_last_row()
{
    const int bn = blockIdx.x;
    const int h = threadIdx.x;
    const int b = bn >> 4, n = bn & 15;
    const float* v = &g_v[(size_t)bn * PP * HD + h];
    float s = 0.f;
    for (int k = 0; k < PP; k++) s += v[(size_t)k * HD];
    g_z[((size_t)(b*PP + (PP-1))*NHEAD + n)*HD + h] = s * (1.0f / PP);
}

// ---------------------------------------------------------------------------
// Output projection (ROUND-5 VERBATIM): out = z @ wo + bias
// ---------------------------------------------------------------------------
__global__ __launch_bounds__(256) void oproj_mma(
    const float* __restrict__ wo, const float* __restrict__ bias,
    float* __restrict__ out)
{
    __shared__ GemmSmem sm;
    const int c0 = blockIdx.x * 64;
    const int r0 = blockIdx.y * 128;
    float acc[8][4] = {};
    gemm128x64(g_z + (size_t)r0*MM, MM, wo + c0, MM, MM, &sm, acc);

    const int tid = threadIdx.x, wid = tid>>5, l = tid&31;
    const int rowa = r0 + wid*16 + (l>>2);
    const int col  = (l&3)*2;
    #pragma unroll
    for (int nt = 0; nt < 8; nt++) {
        int c = c0 + nt*8 + col;
        float2 b2 = *(const float2*)&bias[c];
        *(float2*)&out[(size_t)rowa*MM + c] =
            make_float2(acc[nt][0] + b2.x, acc[nt][1] + b2.y);
        *(float2*)&out[(size_t)(rowa+8)*MM + c] =
            make_float2(acc[nt][2] + b2.x, acc[nt][3] + b2.y);
    }
}

// ---------------------------------------------------------------------------
extern "C" void kernel_launch(void* const* d_in, const int* in_sizes, int n_in,
                              void* d_out, int out_size)
{
    const float* x  = (const float*)d_in[0];
    const float* wq = (const float*)d_in[1];
    const float* wk = (const float*)d_in[2];
    const float* wv = (const float*)d_in[3];
    const float* wo = (const float*)d_in[4];
    const float* bq = (const float*)d_in[5];
    const float* bk = (const float*)d_in[6];
    const float* bv = (const float*)d_in[7];
    const float* bo = (const float*)d_in[8];
    float* out = (float*)d_out;

    cudaFuncSetAttribute(attn_mma, cudaFuncAttributeMaxDynamicSharedMemorySize,
                         (int)sizeof(AttnSmem));

    dim3 gemm_grid(NHEAD, (BB*PP)/128);   // (16, 32)
    qkv_mma<0><<<gemm_grid, 256>>>(x, wq, bq);
    qkv_mma<1><<<gemm_grid, 256>>>(x, wk, bk);
    qkv_mma<2><<<gemm_grid, 256>>>(x, wv, bv);

    attn_mma<<<dim3(PP/128, BB*NHEAD), 256, sizeof(AttnSmem)>>>();
    fix_last_row<<<BB*NHEAD, HD>>>();

    oproj_mma<<<dim3(MM/64, (BB*PP)/128), 256>>>(wo, bo, out);
}

// round 12
// speedup vs baseline: 2.1094x; 1.1842x over previous
#include <cuda_runtime.h>
#include <cuda_bf16.h>
#include <stdint.h>

#define BB 2
#define PP 2048
#define MM 1024
#define NHEAD 16
#define HD 64

// ---------------------------------------------------------------------------
// Globals: 64 MB total (proven envelope).
// q/k/v stored pre-split as bf16 hi/lo (8 MB each half).
// g_z (16 MB) holds x pre-split (hi half | lo half) during QKV,
// then z pre-split (hi half | lo half) after attention.
// ---------------------------------------------------------------------------
__device__ __nv_bfloat16 gq_h[BB*NHEAD*PP*HD], gq_l[BB*NHEAD*PP*HD];
__device__ __nv_bfloat16 gk_h[BB*NHEAD*PP*HD], gk_l[BB*NHEAD*PP*HD];
__device__ __nv_bfloat16 gv_h[BB*NHEAD*PP*HD], gv_l[BB*NHEAD*PP*HD];
__device__ float g_z[BB*PP*MM];
#define GZ_HALF (BB*PP*MM/2)    // u32 elements per half of g_z

// ---------------------------------------------------------------------------
// helpers (round-11 proven)
// ---------------------------------------------------------------------------
__device__ __forceinline__ uint32_t smem_u32(const void* p) {
    uint32_t a;
    asm("{ .reg .u64 t; cvta.to.shared.u64 t, %1; cvt.u32.u64 %0, t; }"
        : "=r"(a) : "l"(p));
    return a;
}
__device__ __forceinline__ void ldsm_x4(uint32_t* r, uint32_t addr) {
    asm volatile("ldmatrix.sync.aligned.m8n8.x4.shared.b16 {%0,%1,%2,%3}, [%4];"
        : "=r"(r[0]), "=r"(r[1]), "=r"(r[2]), "=r"(r[3]) : "r"(addr));
}
__device__ __forceinline__ void ldsm_x4_t(uint32_t* r, uint32_t addr) {
    asm volatile("ldmatrix.sync.aligned.m8n8.x4.trans.shared.b16 {%0,%1,%2,%3}, [%4];"
        : "=r"(r[0]), "=r"(r[1]), "=r"(r[2]), "=r"(r[3]) : "r"(addr));
}
__device__ __forceinline__ void mma_bf16(float* d, const uint32_t* a, const uint32_t* b) {
    asm volatile("mma.sync.aligned.m16n8k16.row.col.f32.bf16.bf16.f32 "
        "{%0,%1,%2,%3}, {%4,%5,%6,%7}, {%8,%9}, {%0,%1,%2,%3};"
        : "+f"(d[0]), "+f"(d[1]), "+f"(d[2]), "+f"(d[3])
        : "r"(a[0]), "r"(a[1]), "r"(a[2]), "r"(a[3]), "r"(b[0]), "r"(b[1]));
}
__device__ __forceinline__ void mma_bf16_s(float* d, const uint32_t* a,
                                           uint32_t b0, uint32_t b1) {
    asm volatile("mma.sync.aligned.m16n8k16.row.col.f32.bf16.bf16.f32 "
        "{%0,%1,%2,%3}, {%4,%5,%6,%7}, {%8,%9}, {%0,%1,%2,%3};"
        : "+f"(d[0]), "+f"(d[1]), "+f"(d[2]), "+f"(d[3])
        : "r"(a[0]), "r"(a[1]), "r"(a[2]), "r"(a[3]), "r"(b0), "r"(b1));
}
__device__ __forceinline__ void split2(float a, float b, uint32_t& hi2, uint32_t& lo2) {
    __nv_bfloat16 ah = __float2bfloat16(a), bh = __float2bfloat16(b);
    float ar = a - __bfloat162float(ah), br = b - __bfloat162float(bh);
    __nv_bfloat162 h; h.x = ah; h.y = bh;
    __nv_bfloat162 l; l.x = __float2bfloat16(ar); l.y = __float2bfloat16(br);
    hi2 = *(uint32_t*)&h; lo2 = *(uint32_t*)&l;
}

// ---------------------------------------------------------------------------
// one-shot: x fp32 -> bf16 hi/lo halves inside g_z
// ---------------------------------------------------------------------------
__global__ void conv_pack_x(const float* __restrict__ x)
{
    uint32_t* xh = (uint32_t*)g_z;
    uint32_t* xl = (uint32_t*)g_z + GZ_HALF;
    int i = blockIdx.x * blockDim.x + threadIdx.x;
    if (i < BB*PP*MM/2) {
        float2 v = ((const float2*)x)[i];
        uint32_t h2, l2; split2(v.x, v.y, h2, l2);
        xh[i] = h2; xl[i] = l2;
    }
}

// ---------------------------------------------------------------------------
// QKV projection, TWO heads per block (N=128 total). A from pre-split x
// (pure u32 staging); B split2 from fp32 weights. 8 warps x 16 rows.
// Output: pre-split bf16 hi/lo q/k/v in [B,N,P,H].
// ---------------------------------------------------------------------------
#define PA_U32 20      // A smem pitch: 80 B
#define PB_U32 36      // B smem pitch: 144 B

struct Qkv2Smem {
    uint32_t Ah[128*PA_U32], Al[128*PA_U32];
    uint32_t Bh[2][32*PB_U32], Bl[2][32*PB_U32];
};  // 38912 B

template<int DST>
__global__ __launch_bounds__(256) void qkv_mma(
    const float* __restrict__ w, const float* __restrict__ bias)
{
    __shared__ Qkv2Smem sm;
    const int hp = blockIdx.x;          // head pair: heads 2hp, 2hp+1
    const int r0 = blockIdx.y * 128;
    const int tid = threadIdx.x;
    const int wid = tid >> 5, l = tid & 31;

    const uint32_t* xh = (const uint32_t*)g_z;
    const uint32_t* xl = (const uint32_t*)g_z + GZ_HALF;

    float acc[2][8][4];
    #pragma unroll
    for (int s = 0; s < 2; s++)
        #pragma unroll
        for (int i = 0; i < 8; i++)
            acc[s][i][0]=acc[s][i][1]=acc[s][i][2]=acc[s][i][3]=0.f;

    const uint32_t ah_b = smem_u32(sm.Ah);
    const uint32_t al_b = smem_u32(sm.Al);
    const int arow = wid*16 + (l & 15);
    const int akb  = (l >> 4) * 16;
    const int brow = (l & 7) + ((l >> 3) & 1) * 8;
    const int bnb  = (l >> 4) * 16;

    for (int k0 = 0; k0 < MM; k0 += 32) {
        // A: pure u32 copies from pre-split x
        #pragma unroll
        for (int t = 0; t < 8; t++) {
            int idx = t*256 + tid;
            int row = idx >> 4, kp = idx & 15;
            size_t pi = (size_t)(r0 + row) * (MM/2) + (k0 >> 1) + kp;
            sm.Ah[row*PA_U32 + kp] = xh[pi];
            sm.Al[row*PA_U32 + kp] = xl[pi];
        }
        // B: 32 k x 64 n-pairs over two heads; split2 from fp32 w
        #pragma unroll
        for (int t = 0; t < 8; t++) {
            int idx = t*256 + tid;
            int kk = idx >> 6, np = idx & 63;
            int s = np >> 5, npl = np & 31;
            int head = 2*hp + s;
            float2 v = *(const float2*)&w[(size_t)head*MM*HD
                                          + (size_t)(k0+kk)*HD + npl*2];
            uint32_t h2, l2; split2(v.x, v.y, h2, l2);
            sm.Bh[s][kk*PB_U32 + npl] = h2;
            sm.Bl[s][kk*PB_U32 + npl] = l2;
        }
        __syncthreads();

        #pragma unroll
        for (int ks = 0; ks < 2; ks++) {
            uint32_t ah[4], al[4];
            uint32_t a_off = (uint32_t)(arow*80 + ks*32 + akb);
            ldsm_x4(ah, ah_b + a_off);
            ldsm_x4(al, al_b + a_off);
            #pragma unroll
            for (int s = 0; s < 2; s++) {
                uint32_t bh_b = smem_u32(sm.Bh[s]);
                uint32_t bl_b = smem_u32(sm.Bl[s]);
                #pragma unroll
                for (int nt2 = 0; nt2 < 4; nt2++) {
                    uint32_t bh[4], bl[4];
                    uint32_t b_off = (uint32_t)((ks*16 + brow)*144 + nt2*32 + bnb);
                    ldsm_x4_t(bh, bh_b + b_off);
                    ldsm_x4_t(bl, bl_b + b_off);
                    mma_bf16(acc[s][nt2*2+0], ah, bh);
                    mma_bf16(acc[s][nt2*2+1], ah, bh+2);
                    mma_bf16(acc[s][nt2*2+0], ah, bl);
                    mma_bf16(acc[s][nt2*2+1], ah, bl+2);
                    mma_bf16(acc[s][nt2*2+0], al, bh);
                    mma_bf16(acc[s][nt2*2+1], al, bh+2);
                }
            }
        }
        __syncthreads();
    }

    // Epilogue: +bias, split to bf16 hi/lo, store both heads
    __nv_bfloat16* Dh = (DST == 0) ? gq_h : (DST == 1) ? gk_h : gv_h;
    __nv_bfloat16* Dl = (DST == 0) ? gq_l : (DST == 1) ? gk_l : gv_l;
    const int rowa = r0 + wid*16 + (l>>2);
    const int col  = (l&3)*2;
    #pragma unroll
    for (int s = 0; s < 2; s++) {
        int head = 2*hp + s;
        #pragma unroll
        for (int nt = 0; nt < 8; nt++) {
            int c = nt*8 + col;
            float2 b2 = *(const float2*)&bias[head*HD + c];
            int r1 = rowa, r2 = rowa + 8;
            int b1_ = r1 >> 11, p1 = r1 & (PP-1);
            int b2_ = r2 >> 11, p2 = r2 & (PP-1);
            size_t i1 = ((size_t)(b1_*NHEAD + head)*PP + p1)*HD + c;
            size_t i2 = ((size_t)(b2_*NHEAD + head)*PP + p2)*HD + c;
            uint32_t h2, l2;
            split2(acc[s][nt][0] + b2.x, acc[s][nt][1] + b2.y, h2, l2);
            ((uint32_t*)Dh)[i1>>1] = h2; ((uint32_t*)Dl)[i1>>1] = l2;
            split2(acc[s][nt][2] + b2.x, acc[s][nt][3] + b2.y, h2, l2);
            ((uint32_t*)Dh)[i2>>1] = h2; ((uint32_t*)Dl)[i2>>1] = l2;
        }
    }
}

// ---------------------------------------------------------------------------
// Tensor-core flash attention (round-11 structure; staging = pure u32 copies
// from pre-split q/k/v; z written pre-split into g_z halves).
// ---------------------------------------------------------------------------
#define AT_P32 36

struct AttnSmem {
    uint32_t Qh[128*AT_P32], Ql[128*AT_P32];
    uint32_t Kh[64*AT_P32],  Kl[64*AT_P32];
    uint32_t Vh[64*AT_P32],  Vl[64*AT_P32];
    uint32_t Ph[128*AT_P32], Pl[128*AT_P32];
};  // 110592 B

extern __shared__ unsigned char dynsmem[];

__global__ __launch_bounds__(256) void attn_mma()
{
    AttnSmem* sm = (AttnSmem*)dynsmem;
    const int q0 = blockIdx.x * 128;
    const int bn = blockIdx.y;
    const size_t base = (size_t)bn * PP * HD;
    const int tid = threadIdx.x;
    const int w = tid >> 5, l = tid & 31;
    const int gid = l >> 2, tid4 = l & 3;

    const uint32_t* qhu = (const uint32_t*)gq_h;
    const uint32_t* qlu = (const uint32_t*)gq_l;
    const uint32_t* khu = (const uint32_t*)gk_h;
    const uint32_t* klu = (const uint32_t*)gk_l;
    const uint32_t* vhu = (const uint32_t*)gv_h;
    const uint32_t* vlu = (const uint32_t*)gv_l;
    uint32_t* zh = (uint32_t*)g_z;
    uint32_t* zl = (uint32_t*)g_z + GZ_HALF;

    // Stage Q: pure u32 copies
    #pragma unroll
    for (int t = 0; t < 16; t++) {
        int idx = t*256 + tid;
        int row = idx >> 5, kp = idx & 31;
        size_t pi = (base + (size_t)(q0+row)*HD) / 2 + kp;
        sm->Qh[row*AT_P32 + kp] = qhu[pi];
        sm->Ql[row*AT_P32 + kp] = qlu[pi];
    }
    __syncthreads();

    float O[8][4];
    #pragma unroll
    for (int i = 0; i < 8; i++) O[i][0]=O[i][1]=O[i][2]=O[i][3]=0.f;
    float m0 = -1e30f, m1 = -1e30f, l0 = 0.f, l1 = 0.f;
    const int row0 = q0 + w*16 + gid, row1 = row0 + 8;

    const uint32_t qh_b = smem_u32(sm->Qh), ql_b = smem_u32(sm->Ql);
    const uint32_t kh_b = smem_u32(sm->Kh), kl_b = smem_u32(sm->Kl);
    const uint32_t vh_b = smem_u32(sm->Vh), vl_b = smem_u32(sm->Vl);
    const uint32_t ph_b = smem_u32(sm->Ph), pl_b = smem_u32(sm->Pl);
    const uint32_t qoff = (uint32_t)(((w*16 + (l&15))*72 + (l>>4)*8) * 2);
    const uint32_t koff = (uint32_t)(((l&15)*72 + (l>>4)*8) * 2);
    const int vrow = (l&7) + ((l>>3)&1)*8;
    const uint32_t voff = (uint32_t)((vrow*72 + (l>>4)*8) * 2);
    const int prow0 = w*16 + gid;

    for (int k0 = q0; k0 < PP; k0 += 64) {
        __syncthreads();
        #pragma unroll
        for (int t = 0; t < 8; t++) {
            int idx = t*256 + tid;
            int row = idx >> 5, kp = idx & 31;
            size_t pi = (base + (size_t)(k0+row)*HD) / 2 + kp;
            sm->Kh[row*AT_P32+kp] = khu[pi];
            sm->Kl[row*AT_P32+kp] = klu[pi];
            sm->Vh[row*AT_P32+kp] = vhu[pi];
            sm->Vl[row*AT_P32+kp] = vlu[pi];
        }
        __syncthreads();

        #pragma unroll
        for (int h2i = 0; h2i < 2; h2i++) {
            float S[4][4];
            #pragma unroll
            for (int i = 0; i < 4; i++) S[i][0]=S[i][1]=S[i][2]=S[i][3]=0.f;
            #pragma unroll
            for (int kf = 0; kf < 4; kf++) {
                uint32_t qh4[4], ql4[4];
                ldsm_x4(qh4, qh_b + qoff + kf*32);
                ldsm_x4(ql4, ql_b + qoff + kf*32);
                #pragma unroll
                for (int kt = 0; kt < 2; kt++) {
                    uint32_t o2 = koff + (uint32_t)((h2i*32 + kt*16)*144 + kf*32);
                    uint32_t kh4[4], kl4[4];
                    ldsm_x4(kh4, kh_b + o2);
                    ldsm_x4(kl4, kl_b + o2);
                    mma_bf16_s(S[2*kt],   qh4, kh4[0], kh4[2]);
                    mma_bf16_s(S[2*kt+1], qh4, kh4[1], kh4[3]);
                    mma_bf16_s(S[2*kt],   qh4, kl4[0], kl4[2]);
                    mma_bf16_s(S[2*kt+1], qh4, kl4[1], kl4[3]);
                    mma_bf16_s(S[2*kt],   ql4, kh4[0], kh4[2]);
                    mma_bf16_s(S[2*kt+1], ql4, kh4[1], kh4[3]);
                }
            }

            #pragma unroll
            for (int nt = 0; nt < 4; nt++) {
                int kb = k0 + h2i*32 + nt*8 + tid4*2;
                S[nt][0] = (kb   > row0) ? S[nt][0]*0.125f : -1e10f;
                S[nt][1] = (kb+1 > row0) ? S[nt][1]*0.125f : -1e10f;
                S[nt][2] = (kb   > row1) ? S[nt][2]*0.125f : -1e10f;
                S[nt][3] = (kb+1 > row1) ? S[nt][3]*0.125f : -1e10f;
            }
            float mx0 = -1e30f, mx1 = -1e30f;
            #pragma unroll
            for (int nt = 0; nt < 4; nt++) {
                mx0 = fmaxf(mx0, fmaxf(S[nt][0], S[nt][1]));
                mx1 = fmaxf(mx1, fmaxf(S[nt][2], S[nt][3]));
            }
            mx0 = fmaxf(mx0, __shfl_xor_sync(0xffffffffu, mx0, 1));
            mx0 = fmaxf(mx0, __shfl_xor_sync(0xffffffffu, mx0, 2));
            mx1 = fmaxf(mx1, __shfl_xor_sync(0xffffffffu, mx1, 1));
            mx1 = fmaxf(mx1, __shfl_xor_sync(0xffffffffu, mx1, 2));
            float mn0 = fmaxf(m0, mx0), mn1 = fmaxf(m1, mx1);
            float a0 = __expf(m0 - mn0), a1 = __expf(m1 - mn1);

            float s0 = 0.f, s1 = 0.f;
            #pragma unroll
            for (int nt = 0; nt < 4; nt++) {
                float p0 = __expf(S[nt][0] - mn0);
                float p1 = __expf(S[nt][1] - mn0);
                float p2 = __expf(S[nt][2] - mn1);
                float p3 = __expf(S[nt][3] - mn1);
                s0 += p0 + p1;
                s1 += p2 + p3;
                uint32_t hh2, ll2;
                split2(p0, p1, hh2, ll2);
                sm->Ph[prow0*AT_P32 + h2i*16 + nt*4 + tid4] = hh2;
                sm->Pl[prow0*AT_P32 + h2i*16 + nt*4 + tid4] = ll2;
                split2(p2, p3, hh2, ll2);
                sm->Ph[(prow0+8)*AT_P32 + h2i*16 + nt*4 + tid4] = hh2;
                sm->Pl[(prow0+8)*AT_P32 + h2i*16 + nt*4 + tid4] = ll2;
            }
            s0 += __shfl_xor_sync(0xffffffffu, s0, 1);
            s0 += __shfl_xor_sync(0xffffffffu, s0, 2);
            s1 += __shfl_xor_sync(0xffffffffu, s1, 1);
            s1 += __shfl_xor_sync(0xffffffffu, s1, 2);
            l0 = l0*a0 + s0;  l1 = l1*a1 + s1;
            m0 = mn0;  m1 = mn1;
            #pragma unroll
            for (int ht = 0; ht < 8; ht++) {
                O[ht][0] *= a0; O[ht][1] *= a0;
                O[ht][2] *= a1; O[ht][3] *= a1;
            }
            __syncwarp();

            #pragma unroll
            for (int kkf = 0; kkf < 2; kkf++) {
                int g = h2i*2 + kkf;
                uint32_t pf_h[4], pf_l[4];
                ldsm_x4(pf_h, ph_b + qoff + g*32);
                ldsm_x4(pf_l, pl_b + qoff + g*32);
                #pragma unroll
                for (int hf = 0; hf < 4; hf++) {
                    uint32_t vh4[4], vl4[4];
                    uint32_t o2 = voff + (uint32_t)(g*16*144 + hf*32);
                    ldsm_x4_t(vh4, vh_b + o2);
                    ldsm_x4_t(vl4, vl_b + o2);
                    mma_bf16_s(O[2*hf],   pf_h, vh4[0], vh4[1]);
                    mma_bf16_s(O[2*hf+1], pf_h, vh4[2], vh4[3]);
                    mma_bf16_s(O[2*hf],   pf_h, vl4[0], vl4[1]);
                    mma_bf16_s(O[2*hf+1], pf_h, vl4[2], vl4[3]);
                    mma_bf16_s(O[2*hf],   pf_l, vh4[0], vh4[1]);
                    mma_bf16_s(O[2*hf+1], pf_l, vh4[2], vh4[3]);
                }
            }
        }
    }

    // epilogue: z = O / l -> bf16 hi/lo halves of g_z, layout [B,P,N,H]
    const int b = bn >> 4, n = bn & 15;
    const float inv0 = 1.f / l0, inv1 = 1.f / l1;
    #pragma unroll
    for (int ht = 0; ht < 8; ht++) {
        int h = ht*8 + tid4*2;
        size_t i0 = ((size_t)(b*PP + row0)*NHEAD + n)*HD + h;
        size_t i1 = ((size_t)(b*PP + row1)*NHEAD + n)*HD + h;
        uint32_t h2, l2;
        split2(O[ht][0]*inv0, O[ht][1]*inv0, h2, l2);
        zh[i0>>1] = h2; zl[i0>>1] = l2;
        split2(O[ht][2]*inv1, O[ht][3]*inv1, h2, l2);
        zh[i1>>1] = h2; zl[i1>>1] = l2;
    }
}

// ---------------------------------------------------------------------------
// Fix-up: row q = P-1 fully masked -> z = mean_k v[k] (pre-split store)
// ---------------------------------------------------------------------------
__global__ void fix_last_row()
{
    const int bn = blockIdx.x;
    const int h = threadIdx.x;          // 64 threads
    const int b = bn >> 4, n = bn & 15;
    size_t vb = (size_t)bn * PP * HD + h;
    float s = 0.f;
    for (int k = 0; k < PP; k++) {
        size_t i = vb + (size_t)k * HD;
        s += __bfloat162float(gv_h[i]) + __bfloat162float(gv_l[i]);
    }
    s *= (1.0f / PP);
    float s_next = __shfl_down_sync(0xffffffffu, s, 1);
    if ((h & 1) == 0) {
        uint32_t h2, l2; split2(s, s_next, h2, l2);
        size_t zi = ((size_t)(b*PP + (PP-1))*NHEAD + n)*HD + h;
        ((uint32_t*)g_z)[zi>>1] = h2;
        (((uint32_t*)g_z) + GZ_HALF)[zi>>1] = l2;
    }
}

// ---------------------------------------------------------------------------
// Output projection, N=128 per block. A from pre-split z (u32 staging),
// B split2 from fp32 wo. fp32 out.
// ---------------------------------------------------------------------------
__global__ __launch_bounds__(256) void oproj_mma(
    const float* __restrict__ wo, const float* __restrict__ bias,
    float* __restrict__ out)
{
    __shared__ Qkv2Smem sm;
    const int c0 = blockIdx.x * 128;
    const int r0 = blockIdx.y * 128;
    const int tid = threadIdx.x;
    const int wid = tid >> 5, l = tid & 31;

    const uint32_t* zh = (const uint32_t*)g_z;
    const uint32_t* zl = (const uint32_t*)g_z + GZ_HALF;

    float acc[2][8][4];
    #pragma unroll
    for (int s = 0; s < 2; s++)
        #pragma unroll
        for (int i = 0; i < 8; i++)
            acc[s][i][0]=acc[s][i][1]=acc[s][i][2]=acc[s][i][3]=0.f;

    const uint32_t ah_b = smem_u32(sm.Ah);
    const uint32_t al_b = smem_u32(sm.Al);
    const int arow = wid*16 + (l & 15);
    const int akb  = (l >> 4) * 16;
    const int brow = (l & 7) + ((l >> 3) & 1) * 8;
    const int bnb  = (l >> 4) * 16;

    for (int k0 = 0; k0 < MM; k0 += 32) {
        #pragma unroll
        for (int t = 0; t < 8; t++) {
            int idx = t*256 + tid;
            int row = idx >> 4, kp = idx & 15;
            size_t pi = (size_t)(r0 + row) * (MM/2) + (k0 >> 1) + kp;
            sm.Ah[row*PA_U32 + kp] = zh[pi];
            sm.Al[row*PA_U32 + kp] = zl[pi];
        }
        #pragma unroll
        for (int t = 0; t < 8; t++) {
            int idx = t*256 + tid;
            int kk = idx >> 6, np = idx & 63;
            int s = np >> 5, npl = np & 31;
            float2 v = *(const float2*)&wo[(size_t)(k0+kk)*MM + c0 + np*2];
            uint32_t h2, l2; split2(v.x, v.y, h2, l2);
            sm.Bh[s][kk*PB_U32 + npl] = h2;
            sm.Bl[s][kk*PB_U32 + npl] = l2;
        }
        __syncthreads();

        #pragma unroll
        for (int ks = 0; ks < 2; ks++) {
            uint32_t ah[4], al[4];
            uint32_t a_off = (uint32_t)(arow*80 + ks*32 + akb);
            ldsm_x4(ah, ah_b + a_off);
            ldsm_x4(al, al_b + a_off);
            #pragma unroll
            for (int s = 0; s < 2; s++) {
                uint32_t bh_b = smem_u32(sm.Bh[s]);
                uint32_t bl_b = smem_u32(sm.Bl[s]);
                #pragma unroll
                for (int nt2 = 0; nt2 < 4; nt2++) {
                    uint32_t bh[4], bl[4];
                    uint32_t b_off = (uint32_t)((ks*16 + brow)*144 + nt2*32 + bnb);
                    ldsm_x4_t(bh, bh_b + b_off);
                    ldsm_x4_t(bl, bl_b + b_off);
                    mma_bf16(acc[s][nt2*2+0], ah, bh);
                    mma_bf16(acc[s][nt2*2+1], ah, bh+2);
                    mma_bf16(acc[s][nt2*2+0], ah, bl);
                    mma_bf16(acc[s][nt2*2+1], ah, bl+2);
                    mma_bf16(acc[s][nt2*2+0], al, bh);
                    mma_bf16(acc[s][nt2*2+1], al, bh+2);
                }
            }
        }
        __syncthreads();
    }

    const int rowa = r0 + wid*16 + (l>>2);
    const int col  = (l&3)*2;
    #pragma unroll
    for (int s = 0; s < 2; s++) {
        #pragma unroll
        for (int nt = 0; nt < 8; nt++) {
            int c = c0 + s*64 + nt*8 + col;
            float2 b2 = *(const float2*)&bias[c];
            *(float2*)&out[(size_t)rowa*MM + c] =
                make_float2(acc[s][nt][0] + b2.x, acc[s][nt][1] + b2.y);
            *(float2*)&out[(size_t)(rowa+8)*MM + c] =
                make_float2(acc[s][nt][2] + b2.x, acc[s][nt][3] + b2.y);
        }
    }
}

// ---------------------------------------------------------------------------
extern "C" void kernel_launch(void* const* d_in, const int* in_sizes, int n_in,
                              void* d_out, int out_size)
{
    const float* x  = (const float*)d_in[0];
    const float* wq = (const float*)d_in[1];
    const float* wk = (const float*)d_in[2];
    const float* wv = (const float*)d_in[3];
    const float* wo = (const float*)d_in[4];
    const float* bq = (const float*)d_in[5];
    const float* bk = (const float*)d_in[6];
    const float* bv = (const float*)d_in[7];
    const float* bo = (const float*)d_in[8];
    float* out = (float*)d_out;

    cudaFuncSetAttribute(attn_mma, cudaFuncAttributeMaxDynamicSharedMemorySize,
                         (int)sizeof(AttnSmem));

    conv_pack_x<<<(BB*PP*MM/2 + 255)/256, 256>>>(x);

    dim3 gemm_grid(NHEAD/2, (BB*PP)/128);   // (8, 32)
    qkv_mma<0><<<gemm_grid, 256>>>(wq, bq);
    qkv_mma<1><<<gemm_grid, 256>>>(wk, bk);
    qkv_mma<2><<<gemm_grid, 256>>>(wv, bv);

    attn_mma<<<dim3(PP/128, BB*NHEAD), 256, sizeof(AttnSmem)>>>();
    fix_last_row<<<BB*NHEAD, HD>>>();

    oproj_mma<<<dim3(MM/128, (BB*PP)/128), 256>>>(wo, bo, out);
}